// round 6
// baseline (speedup 1.0000x reference)
#include <cuda_runtime.h>
#include <cstdint>

// FlowNetC correlation cost volume.
// Shapes (from reference setup_inputs): input [B=8, C=128, H=128, W=256] fp32.
// out[b, (dy+4)*9+(dx+4), y, x] = (1/128) * sum_c in1[b,c,y,x] * in2z[b,c,y+dy,x+dx]
// where in2z is zero outside [0,H)x[0,W) (PAD=4 >= max displacement 4, so the
// reference's padding reduces to zero-fill at the borders).
//
// Block = (dy, y-tile of 4 rows, batch). 256 threads; thread <-> (row, x-quad).
// - 36 fp32 accumulators per thread (9 dx * 4 x), live across the channel loop.
// - in1 'a': direct LDG.128 (always in-bounds; dy is the fastest grid dim so the
//   9 dy-blocks sharing a (b, ytile) run adjacently and reuse in1 through L2).
// - in2 'b': staged to shared in 8-channel chunks, double-buffered cp.async;
//   rows padded to 264 cols with pre-zeroed 4-col halos -> OOB handling is free.

#define B_      8
#define C_      128
#define H_      128
#define W_      256
#define CHUNK   8             // channels per smem chunk
#define RTILE   4             // output rows per block
#define THREADS 256
#define IN2_ROW (W_ + 8)      // 264: cols -4..259 (4-col halo each side)
#define BUF_FLOATS (CHUNK * RTILE * IN2_ROW)   // 8448 floats = 33,792 B
#define SMEM_BYTES (2 * BUF_FLOATS * 4)        // 67,584 B (double buffer)

__device__ __forceinline__ void cp_async16(void* dst_smem, const void* src_gmem) {
    uint32_t d = (uint32_t)__cvta_generic_to_shared(dst_smem);
    asm volatile("cp.async.cg.shared.global [%0], [%1], 16;"
                 :: "r"(d), "l"(src_gmem) : "memory");
}
__device__ __forceinline__ void cp_commit() {
    asm volatile("cp.async.commit_group;" ::: "memory");
}
template <int N>
__device__ __forceinline__ void cp_wait() {
    asm volatile("cp.async.wait_group %0;" :: "n"(N) : "memory");
}

extern __shared__ float s_mem[];

__global__ __launch_bounds__(THREADS, 2)
void corr_kernel(const float* __restrict__ in1,
                 const float* __restrict__ in2,
                 float* __restrict__ out)
{
    const int dy  = (int)blockIdx.x - 4;       // -4..4
    const int y0  = (int)blockIdx.y * RTILE;   // 0,4,...,124
    const int b   = (int)blockIdx.z;
    const int tid = (int)threadIdx.x;

    const float* in1b = in1 + (size_t)b * C_ * H_ * W_;
    const float* in2b = in2 + (size_t)b * C_ * H_ * W_;

    float* buf0 = s_mem;
    float* buf1 = s_mem + BUF_FLOATS;

    // Pre-zero both buffers: column halos (cols 0..3, 260..263) and rows whose
    // y+dy falls outside [0,H) are never overwritten and stay zero.
    for (int i = tid; i < 2 * BUF_FLOATS; i += THREADS) s_mem[i] = 0.0f;
    __syncthreads();

    const int row = tid >> 6;          // 0..3
    const int x   = (tid & 63) * 4;    // 0,4,...,252

    float acc[9][4];
#pragma unroll
    for (int d = 0; d < 9; ++d)
#pragma unroll
        for (int i = 0; i < 4; ++i) acc[d][i] = 0.0f;

    // ---- staging: in-bounds float4s of in2 rows [y0+dy .. y0+dy+3] ----
    auto stage = [&](int c0, float* buf) {
#pragma unroll
        for (int it = 0; it < (CHUNK * RTILE * (W_ / 4)) / THREADS; ++it) {
            int i  = tid + it * THREADS;       // 0..2047
            int c  = i >> 8;                   // / (RTILE * 64) -> 0..7
            int rr = (i >> 6) & (RTILE - 1);   // 0..3
            int f4 = i & 63;                   // 0..63 -> global x = 4*f4
            int gy = y0 + dy + rr;
            if ((unsigned)gy < (unsigned)H_) {
                const float* src = in2b + (((size_t)(c0 + c) * H_ + gy) * W_ + f4 * 4);
                float* dst = buf + ((c * RTILE + rr) * IN2_ROW + 4 + f4 * 4);
                cp_async16(dst, src);
            }
        }
    };

    stage(0, buf0);
    cp_commit();

    const int NCHUNK = C_ / CHUNK;   // 16
    for (int k = 0; k < NCHUNK; ++k) {
        if (k + 1 < NCHUNK) {
            stage((k + 1) * CHUNK, (k & 1) ? buf0 : buf1);
            cp_commit();
            cp_wait<1>();            // chunk k's group complete
        } else {
            cp_wait<0>();
        }
        __syncthreads();

        const float* buf = (k & 1) ? buf1 : buf0;
        const float* aptr = in1b + (((size_t)(k * CHUNK) * H_ + (y0 + row)) * W_ + x);

#pragma unroll
        for (int c = 0; c < CHUNK; ++c) {
            float4 a = *reinterpret_cast<const float4*>(aptr + (size_t)c * H_ * W_);
            // shared col (x + 4) <-> global col x; brow[j] <-> global x - 4 + j
            const float* brow = buf + (c * RTILE + row) * IN2_ROW + x;
            float4 b0 = *reinterpret_cast<const float4*>(brow);
            float4 b1 = *reinterpret_cast<const float4*>(brow + 4);
            float4 b2 = *reinterpret_cast<const float4*>(brow + 8);
            float bb[12] = {b0.x, b0.y, b0.z, b0.w,
                            b1.x, b1.y, b1.z, b1.w,
                            b2.x, b2.y, b2.z, b2.w};
            float aa[4] = {a.x, a.y, a.z, a.w};
#pragma unroll
            for (int d = 0; d < 9; ++d)         // d = dx + 4
#pragma unroll
                for (int i = 0; i < 4; ++i)     // bb[i+d] <-> global (x+i) + dx
                    acc[d][i] = fmaf(aa[i], bb[i + d], acc[d][i]);
        }
        __syncthreads();   // consumed buffer safe to overwrite next iteration
    }

    // ---- epilogue: scale by 1/C, vectorized stores ----
    const float sc = 1.0f / (float)C_;
    size_t obase = ((((size_t)b * 81 + (size_t)(dy + 4) * 9) * H_ + (y0 + row)) * W_ + x);
#pragma unroll
    for (int d = 0; d < 9; ++d) {
        float4 v = make_float4(acc[d][0] * sc, acc[d][1] * sc,
                               acc[d][2] * sc, acc[d][3] * sc);
        *reinterpret_cast<float4*>(out + obase + (size_t)d * H_ * W_) = v;
    }
}

extern "C" void kernel_launch(void* const* d_in, const int* in_sizes, int n_in,
                              void* d_out, int out_size)
{
    const float* in1 = (const float*)d_in[0];
    const float* in2 = (const float*)d_in[1];
    float* out = (float*)d_out;

    cudaFuncSetAttribute(corr_kernel,
                         cudaFuncAttributeMaxDynamicSharedMemorySize, SMEM_BYTES);

    dim3 grid(9, H_ / RTILE, B_);   // (dy, y-tile, batch); dy fastest -> L2 reuse
    corr_kernel<<<grid, THREADS, SMEM_BYTES>>>(in1, in2, out);
}

// round 8
// speedup vs baseline: 1.2239x; 1.2239x over previous
#include <cuda_runtime.h>
#include <cstdint>

// FlowNetC correlation cost volume. Inputs [B=8, C=128, H=128, W=256] fp32.
// out[b, (dy+4)*9+(dx+4), y, x] = (1/128) * sum_c in1[b,c,y,x] * in2z[b,c,y+dy,x+dx]
// (in2z zero outside bounds; PAD=4 >= max displacement.)
//
// R7 design: warp-autonomous, zero block barriers in the main loop.
// Block = 8 warps; warp w owns output row y0+w and a 128-col half (xh).
// Each warp stages its own in2 row window (cols xbase-4 .. xbase+131, zero
// halos) into warp-private double-buffered smem via cp.async, synchronized
// only by its own wait_group + __syncwarp. Even-dx pairs use packed
// fma.rn.f32x2 (operands are the natural float2 halves of LDS.128 results);
// odd-dx stays scalar FFMA. 26 fma issues/channel/thread vs 36 scalar.

#define B_     8
#define C_     128
#define H_     128
#define W_     256
#define CHUNK  8                    // channels per staged chunk
#define ROWF   136                  // floats per channel-row (4-col halo each side)
#define PHASEF (CHUNK * ROWF)       // 1088 floats per phase
#define WARPBUF (2 * PHASEF)        // 2176 floats per warp (double buffer)
#define SMEM_BYTES (8 * WARPBUF * 4)  // 69,632 B per block

__device__ __forceinline__ void cp_async16(void* dst_smem, const void* src_gmem) {
    uint32_t d = (uint32_t)__cvta_generic_to_shared(dst_smem);
    asm volatile("cp.async.cg.shared.global [%0], [%1], 16;"
                 :: "r"(d), "l"(src_gmem) : "memory");
}
__device__ __forceinline__ void cp_commit() {
    asm volatile("cp.async.commit_group;" ::: "memory");
}
template <int N>
__device__ __forceinline__ void cp_wait() {
    asm volatile("cp.async.wait_group %0;" :: "n"(N) : "memory");
}
__device__ __forceinline__ unsigned long long pk2(float lo, float hi) {
    unsigned long long r;
    asm("mov.b64 %0, {%1, %2};" : "=l"(r) : "f"(lo), "f"(hi));
    return r;
}
__device__ __forceinline__ void fma2(unsigned long long& d,
                                     unsigned long long a, unsigned long long b) {
    asm("fma.rn.f32x2 %0, %1, %2, %0;" : "+l"(d) : "l"(a), "l"(b));
}
__device__ __forceinline__ float2 up2(unsigned long long v) {
    float2 r;
    asm("mov.b64 {%0, %1}, %2;" : "=f"(r.x), "=f"(r.y) : "l"(v));
    return r;
}

extern __shared__ float s_mem[];

__global__ __launch_bounds__(256, 2)
void corr_kernel(const float* __restrict__ in1,
                 const float* __restrict__ in2,
                 float* __restrict__ out)
{
    const int dy    = (int)blockIdx.x - 4;        // -4..4
    const int y0    = (int)blockIdx.y * 8;        // 8 rows per block (1 per warp)
    const int b     = (int)blockIdx.z >> 1;
    const int xh    = (int)blockIdx.z & 1;        // which 128-col half
    const int xbase = xh << 7;
    const int w     = (int)threadIdx.x >> 5;      // warp id = row within tile
    const int lane  = (int)threadIdx.x & 31;
    const int y     = y0 + w;
    const int gy    = y + dy;
    const bool rowok = (unsigned)gy < (unsigned)H_;

    const float* in1b = in1 + (size_t)b * C_ * H_ * W_;
    // base of this warp's in2 row (channel 0); advance by c*H_*W_ per channel
    const float* in2g = in2 + (size_t)b * C_ * H_ * W_ + (size_t)(rowok ? gy : 0) * W_;

    float* wbuf = s_mem + w * WARPBUF;

    // Zero the warp-private buffer once: halo float4s (slot 0 on the left half,
    // slot 33 on the right half) and fully-OOB rows are never overwritten.
    for (int i = lane; i < WARPBUF; i += 32) wbuf[i] = 0.0f;
    __syncwarp();   // order zero-stores before any cp.async overwrites land

    unsigned long long acc2[5][2];   // even d = 2e: packed pairs (x0,x1),(x2,x3)
    float acco[4][4];                // odd  d = 2e+1: scalar
#pragma unroll
    for (int e = 0; e < 5; ++e) { acc2[e][0] = 0ull; acc2[e][1] = 0ull; }
#pragma unroll
    for (int e = 0; e < 4; ++e)
#pragma unroll
        for (int i = 0; i < 4; ++i) acco[e][i] = 0.0f;

    // Stage CHUNK channels of this warp's in2 row into phase ph.
    // Buffer float j <-> global col xbase - 4 + j. Slots are float4s:
    // slot s <-> global float4 index g0 + s, valid iff 0 <= g0+s < 64.
    const int g0 = (xh << 5) - 1;
    auto stage = [&](int c0, int ph) {
        if (!rowok) return;                       // buffer stays all-zero
        float* pb = wbuf + ph * PHASEF;
#pragma unroll
        for (int c = 0; c < CHUNK; ++c) {
            const float* src = in2g + (size_t)(c0 + c) * H_ * W_;
            float* drow = pb + c * ROWF;
            int gf4 = g0 + lane;                  // slots 0..31
            if ((unsigned)gf4 < 64u)
                cp_async16(drow + (lane << 2), src + (gf4 << 2));
            if (lane < 2) {                       // slots 32..33
                int gf4b = g0 + 32 + lane;
                if ((unsigned)gf4b < 64u)
                    cp_async16(drow + ((32 + lane) << 2), src + (gf4b << 2));
            }
        }
    };

    stage(0, 0);
    cp_commit();

    const int NCHUNK = C_ / CHUNK;   // 16
#pragma unroll 2
    for (int k = 0; k < NCHUNK; ++k) {
        if (k < NCHUNK - 1) {
            stage((k + 1) * CHUNK, (k + 1) & 1);
            cp_commit();
            cp_wait<1>();            // chunk k's group complete
        } else {
            cp_wait<0>();
        }
        __syncwarp();                // warp-local visibility of staged data

        const float* pb   = wbuf + (k & 1) * PHASEF;
        const float* aptr = in1b + ((size_t)(k * CHUNK) * H_ + y) * W_
                                 + xbase + (lane << 2);

#pragma unroll
        for (int c = 0; c < CHUNK; ++c) {
            float4 a = *reinterpret_cast<const float4*>(aptr + (size_t)c * H_ * W_);
            const float* br = pb + c * ROWF + (lane << 2);   // bb[j] <-> col x-4+j
            float4 b0 = *reinterpret_cast<const float4*>(br);
            float4 b1 = *reinterpret_cast<const float4*>(br + 4);
            float4 b2 = *reinterpret_cast<const float4*>(br + 8);
            float bb[12] = {b0.x, b0.y, b0.z, b0.w,
                            b1.x, b1.y, b1.z, b1.w,
                            b2.x, b2.y, b2.z, b2.w};

            // packed operands: bp[q] = (bb[2q], bb[2q+1]) -- aligned halves of
            // the LDS.128 results, so these movs collapse to register pairs.
            unsigned long long bp[6];
#pragma unroll
            for (int q = 0; q < 6; ++q) bp[q] = pk2(bb[2 * q], bb[2 * q + 1]);
            unsigned long long a2lo = pk2(a.x, a.y);
            unsigned long long a2hi = pk2(a.z, a.w);

            // even d = 2e: acc2[e][p] += (a[2p],a[2p+1]) * (bb[2p+2e],bb[2p+1+2e])
#pragma unroll
            for (int e = 0; e < 5; ++e) {
                fma2(acc2[e][0], a2lo, bp[e]);
                fma2(acc2[e][1], a2hi, bp[e + 1]);
            }
            // odd d = 2e+1: scalar
            float aa[4] = {a.x, a.y, a.z, a.w};
#pragma unroll
            for (int e = 0; e < 4; ++e)
#pragma unroll
                for (int i = 0; i < 4; ++i)
                    acco[e][i] = fmaf(aa[i], bb[i + 2 * e + 1], acco[e][i]);
        }
        // no trailing barrier: this warp's LDS of chunk k complete ~29cyc after
        // issue; the earliest async overwrite of this buffer (chunk k+2, issued
        // next iteration) lands >=234cyc after its issue.
    }

    // ---- epilogue: scale by 1/C, one float4 store per displacement ----
    const float sc = 1.0f / (float)C_;
    size_t ob = (((size_t)b * 81 + (size_t)(dy + 4) * 9) * H_ + y) * W_
              + xbase + (lane << 2);
#pragma unroll
    for (int e = 0; e < 5; ++e) {                 // d = 2e
        float2 lo = up2(acc2[e][0]), hi = up2(acc2[e][1]);
        float4 v = make_float4(lo.x * sc, lo.y * sc, hi.x * sc, hi.y * sc);
        *reinterpret_cast<float4*>(out + ob + (size_t)(2 * e) * H_ * W_) = v;
    }
#pragma unroll
    for (int e = 0; e < 4; ++e) {                 // d = 2e+1
        float4 v = make_float4(acco[e][0] * sc, acco[e][1] * sc,
                               acco[e][2] * sc, acco[e][3] * sc);
        *reinterpret_cast<float4*>(out + ob + (size_t)(2 * e + 1) * H_ * W_) = v;
    }
}

extern "C" void kernel_launch(void* const* d_in, const int* in_sizes, int n_in,
                              void* d_out, int out_size)
{
    const float* in1 = (const float*)d_in[0];
    const float* in2 = (const float*)d_in[1];
    float* out = (float*)d_out;

    cudaFuncSetAttribute(corr_kernel,
                         cudaFuncAttributeMaxDynamicSharedMemorySize, SMEM_BYTES);

    // (dy, y-tile, b*2+xhalf); dy fastest -> adjacent blocks reuse in1/in2 in L2
    dim3 grid(9, H_ / 8, B_ * 2);
    corr_kernel<<<grid, 256, SMEM_BYTES>>>(in1, in2, out);
}